// round 5
// baseline (speedup 1.0000x reference)
#include <cuda_runtime.h>
#include <cstdint>

// Problem constants
#define N_PIX   131072      // 32 * 64 * 64 pixels (B*H*W)
#define K_CODES 512
#define D_DIM   64
#define TPB     512
#define PIX_PER_BLK TPB                 // 1 pixel per thread
#define NBLK    (N_PIX / PIX_PER_BLK)   // 256

// Output layout (float32 concat in reference return order):
#define OFF_LOSS 0ULL
#define OFF_Q    1ULL
#define OFF_PERP 8388609ULL
#define OFF_ENC  8388610ULL
#define OFF_IDX  75497474ULL

// zeroed each call via one cudaMemsetAsync (graph-capturable memset node)
struct Scratch {
    int    counts[K_CODES];
    double sumsq;
    int    ticket;
};
__device__ Scratch g_s;

// ---------- packed f32x2 helpers (sm_103a FFMA2 via PTX only) ----------
__device__ __forceinline__ unsigned long long fma2(unsigned long long a,
                                                   unsigned long long b,
                                                   unsigned long long c) {
    unsigned long long d;
    asm("fma.rn.f32x2 %0, %1, %2, %3;" : "=l"(d) : "l"(a), "l"(b), "l"(c));
    return d;
}
__device__ __forceinline__ unsigned long long pack2(float lo, float hi) {
    unsigned long long d;
    asm("mov.b64 %0, {%1, %2};" : "=l"(d) : "f"(lo), "f"(hi));
    return d;
}
__device__ __forceinline__ void unpack2(unsigned long long v, float& lo, float& hi) {
    asm("mov.b64 {%0, %1}, %2;" : "=f"(lo), "=f"(hi) : "l"(v));
}

extern __shared__ float4 smem_raw4[];

__global__ __launch_bounds__(TPB, 1) void vq_fused(const float* __restrict__ z,
                                                   const float* __restrict__ emb,
                                                   float* __restrict__ out) {
    // dynamic smem: [0,131072) codebook | [131072,133120) sume | [133120,135168) idx (512)
    char*  smem_raw = (char*)smem_raw4;
    float* s_emb = (float*)smem_raw;
    float* s_se  = (float*)(smem_raw + 131072);
    int*   s_idx = (int*)  (smem_raw + 133120);
    __shared__ double s_red[TPB];

    const int tid = threadIdx.x;

    // ---- stage codebook into smem (8192 float4, 512 threads x 16) ----
    {
        const float4* e4 = (const float4*)emb;
        float4* s4 = (float4*)s_emb;
#pragma unroll
        for (int i = 0; i < 16; i++) s4[tid + i * 512] = e4[tid + i * 512];
    }
    __syncthreads();

    // ---- per-block ||e_k||^2 (one row per thread, sequential ref order) ----
    {
        const float* row = s_emb + tid * D_DIM;
        float s = 0.f;
#pragma unroll
        for (int c = 0; c < D_DIM; c++)
            s = __fadd_rn(s, __fmul_rn(row[c], row[c]));
        s_se[tid] = s;
    }
    __syncthreads();

    // ---- load z for 1 pixel, compute ||z||^2 sequentially (ref-order) ----
    const int n0 = blockIdx.x * PIX_PER_BLK + tid;   // pixel id
    const size_t zb0 = (size_t)(n0 >> 12) * 262144 + (size_t)((n0 >> 6) & 63) * 64 + (n0 & 63);
    const float* zg0 = z + zb0;

    unsigned long long zp0[32];
    float sumz0 = 0.f;
#pragma unroll
    for (int i = 0; i < 32; i++) {
        float a = zg0[(2 * i) * 4096];
        float c = zg0[(2 * i + 1) * 4096];
        sumz0 = __fadd_rn(sumz0, __fmul_rn(a, a));
        sumz0 = __fadd_rn(sumz0, __fmul_rn(c, c));
        zp0[i] = pack2(a, c);
    }

    // ---- argmin over 512 codes (FP order identical to passing kernel) ----
    float best0 = 3.4e38f;
    int bidx0 = 0;
    const ulonglong2* s2 = (const ulonglong2*)s_emb;
#pragma unroll 1
    for (int k = 0; k < K_CODES; k++) {
        const ulonglong2* row = s2 + k * 16;
        unsigned long long a00 = 0ULL, a01 = 0ULL;
#pragma unroll
        for (int i = 0; i < 16; i++) {
            ulonglong2 ev = row[i];
            a00 = fma2(zp0[2 * i],     ev.x, a00);
            a01 = fma2(zp0[2 * i + 1], ev.y, a01);
        }
        float p0, p1, p2, p3;
        unpack2(a00, p0, p1);
        unpack2(a01, p2, p3);
        float dot  = __fadd_rn(__fadd_rn(p0, p1), __fadd_rn(p2, p3));
        float dist = __fsub_rn(__fadd_rn(sumz0, s_se[k]), __fmul_rn(2.0f, dot));
        if (dist < best0) { best0 = dist; bidx0 = k; }
    }

    s_idx[tid] = bidx0;

    // ---- quantized_st = fl(z + fl(q - z)), accumulate (q - z)^2 ----
    float lsum0 = 0.f;
    {
        float* qout = out + OFF_Q + zb0;
        const float* erow = s_emb + bidx0 * D_DIM;
#pragma unroll
        for (int i = 0; i < 32; i++) {
            float zlo, zhi;
            unpack2(zp0[i], zlo, zhi);
            float d0 = __fsub_rn(erow[2 * i],     zlo);
            float d1 = __fsub_rn(erow[2 * i + 1], zhi);
            lsum0 += d0 * d0 + d1 * d1;
            qout[(2 * i) * 4096]     = __fadd_rn(zlo, d0);
            qout[(2 * i + 1) * 4096] = __fadd_rn(zhi, d1);
        }
    }

    out[OFF_IDX + (size_t)n0] = (float)bidx0;
    atomicAdd(&g_s.counts[bidx0], 1);

    // ---- block-reduce squared error (double), one atomic per block ----
    s_red[tid] = (double)lsum0;
    __syncthreads();                 // also publishes s_idx
#pragma unroll
    for (int off = 256; off > 0; off >>= 1) {
        if (tid < off) s_red[tid] += s_red[tid + off];
        __syncthreads();
    }
    if (tid == 0) atomicAdd(&g_s.sumsq, s_red[0]);

    // ---- cooperative coalesced one-hot writes (float2: OFF_ENC is 8B-aligned) ----
    const int lane = tid & 31;
    const int warp = tid >> 5;
    const size_t enc_base = OFF_ENC + (size_t)(blockIdx.x * PIX_PER_BLK) * K_CODES;
    for (int r = warp * 32; r < warp * 32 + 32; r++) {
        const int target = s_idx[r];
        float2* rowp = (float2*)(out + enc_base + (size_t)r * K_CODES);
#pragma unroll
        for (int j = lane; j < 256; j += 32) {
            int c0 = j * 2;
            float2 v;
            v.x = (c0     == target) ? 1.f : 0.f;
            v.y = (c0 + 1 == target) ? 1.f : 0.f;
            rowp[j] = v;
        }
    }

    // ---- last block finalizes loss + perplexity ----
    __shared__ int s_last;
    __threadfence();
    __syncthreads();
    if (tid == 0) s_last = (atomicAdd(&g_s.ticket, 1) == NBLK - 1) ? 1 : 0;
    __syncthreads();
    if (s_last) {
        __threadfence();
        float pf = (float)g_s.counts[tid] * (1.0f / 131072.0f);
        s_red[tid] = (double)(pf * logf(pf + 1e-10f));
        __syncthreads();
#pragma unroll
        for (int off = 256; off > 0; off >>= 1) {
            if (tid < off) s_red[tid] += s_red[tid + off];
            __syncthreads();
        }
        if (tid == 0) {
            out[OFF_PERP] = expf((float)(-s_red[0]));
            double m = g_s.sumsq / 8388608.0;
            float mf = (float)m;
            out[OFF_LOSS] = __fadd_rn(mf, __fmul_rn(0.25f, mf));
        }
    }
}

extern "C" void kernel_launch(void* const* d_in, const int* in_sizes, int n_in,
                              void* d_out, int out_size) {
    const float* z   = (const float*)d_in[0];   // latent_z [32,64,64,64]
    const float* emb = (const float*)d_in[1];   // embedding [512,64]
    float* out = (float*)d_out;

    void* sp = nullptr;
    cudaGetSymbolAddress(&sp, g_s);
    cudaMemsetAsync(sp, 0, sizeof(Scratch), 0);

    const int dyn_smem = 135168;  // 128KB codebook + 2KB norms + 2KB idx
    cudaFuncSetAttribute(vq_fused, cudaFuncAttributeMaxDynamicSharedMemorySize, dyn_smem);
    vq_fused<<<NBLK, TPB, dyn_smem>>>(z, emb, out);
}

// round 8
// speedup vs baseline: 1.3025x; 1.3025x over previous
#include <cuda_runtime.h>
#include <cstdint>

// Problem constants
#define N_PIX   131072      // 32 * 64 * 64 pixels (B*H*W)
#define K_CODES 512
#define D_DIM   64
#define TPB     256
#define PPT     2                       // pixels per thread
#define PIX_PER_BLK (TPB * PPT)         // 512
#define NBLK    (N_PIX / PIX_PER_BLK)   // 256

// Output layout (float32 concat in reference return order):
#define OFF_LOSS 0ULL
#define OFF_Q    1ULL
#define OFF_PERP 8388609ULL
#define OFF_ENC  8388610ULL
#define OFF_IDX  75497474ULL

// zeroed each call via one cudaMemsetAsync (graph-capturable memset node)
struct Scratch {
    int    counts[K_CODES];
    double sumsq;
    int    ticket;
};
__device__ Scratch g_s;

// ---------- packed f32x2 helpers (sm_103a FFMA2 via PTX only) ----------
__device__ __forceinline__ unsigned long long fma2(unsigned long long a,
                                                   unsigned long long b,
                                                   unsigned long long c) {
    unsigned long long d;
    asm("fma.rn.f32x2 %0, %1, %2, %3;" : "=l"(d) : "l"(a), "l"(b), "l"(c));
    return d;
}
__device__ __forceinline__ unsigned long long pack2(float lo, float hi) {
    unsigned long long d;
    asm("mov.b64 %0, {%1, %2};" : "=l"(d) : "f"(lo), "f"(hi));
    return d;
}
__device__ __forceinline__ void unpack2(unsigned long long v, float& lo, float& hi) {
    asm("mov.b64 {%0, %1}, %2;" : "=f"(lo), "=f"(hi) : "l"(v));
}

extern __shared__ float4 smem_raw4[];

__global__ __launch_bounds__(TPB, 1) void vq_fused(const float* __restrict__ z,
                                                   const float* __restrict__ emb,
                                                   float* __restrict__ out) {
    // dynamic smem: [0,131072) codebook | [131072,133120) sume | [133120,135168) idx (512)
    char*  smem_raw = (char*)smem_raw4;
    float* s_emb = (float*)smem_raw;
    float* s_se  = (float*)(smem_raw + 131072);
    int*   s_idx = (int*)  (smem_raw + 133120);
    __shared__ double s_red[TPB];

    const int tid = threadIdx.x;

    // ---- stage codebook into smem (8192 float4) ----
    {
        const float4* e4 = (const float4*)emb;
        float4* s4 = (float4*)s_emb;
#pragma unroll
        for (int i = 0; i < 32; i++) s4[tid + i * 256] = e4[tid + i * 256];
    }
    __syncthreads();

    // ---- per-block ||e_k||^2 (sequential, ref order) ----
    for (int r = tid; r < K_CODES; r += TPB) {
        const float* row = s_emb + r * D_DIM;
        float s = 0.f;
#pragma unroll
        for (int c = 0; c < D_DIM; c++)
            s = __fadd_rn(s, __fmul_rn(row[c], row[c]));
        s_se[r] = s;
    }
    __syncthreads();

    // ---- load z for 2 pixels, compute ||z||^2 sequentially (ref-order) ----
    const int n0 = blockIdx.x * PIX_PER_BLK + tid;   // pixel ids
    const int n1 = n0 + TPB;
    const size_t zb0 = (size_t)(n0 >> 12) * 262144 + (size_t)((n0 >> 6) & 63) * 64 + (n0 & 63);
    const size_t zb1 = (size_t)(n1 >> 12) * 262144 + (size_t)((n1 >> 6) & 63) * 64 + (n1 & 63);
    const float* zg0 = z + zb0;
    const float* zg1 = z + zb1;

    unsigned long long zp0[32], zp1[32];
    float sumz0 = 0.f, sumz1 = 0.f;
#pragma unroll
    for (int i = 0; i < 32; i++) {
        float a = zg0[(2 * i) * 4096];
        float c = zg0[(2 * i + 1) * 4096];
        sumz0 = __fadd_rn(sumz0, __fmul_rn(a, a));
        sumz0 = __fadd_rn(sumz0, __fmul_rn(c, c));
        zp0[i] = pack2(a, c);
    }
#pragma unroll
    for (int i = 0; i < 32; i++) {
        float a = zg1[(2 * i) * 4096];
        float c = zg1[(2 * i + 1) * 4096];
        sumz1 = __fadd_rn(sumz1, __fmul_rn(a, a));
        sumz1 = __fadd_rn(sumz1, __fmul_rn(c, c));
        zp1[i] = pack2(a, c);
    }

    // ---- argmin over 512 codes, 2 codes per iteration (8 fma chains) ----
    // FP chain per (pixel, code) is bit-identical to the passing kernel;
    // codes evaluated in ascending order so strict-< tie semantics hold.
    float best0 = 3.4e38f, best1 = 3.4e38f;
    int bidx0 = 0, bidx1 = 0;
    const ulonglong2* s2 = (const ulonglong2*)s_emb;
#pragma unroll 1
    for (int k = 0; k < K_CODES; k += 2) {
        const ulonglong2* rowA = s2 + k * 16;
        const ulonglong2* rowB = rowA + 16;
        const float seA = s_se[k];
        const float seB = s_se[k + 1];
        unsigned long long a00 = 0ULL, a01 = 0ULL, a10 = 0ULL, a11 = 0ULL;
        unsigned long long b00 = 0ULL, b01 = 0ULL, b10 = 0ULL, b11 = 0ULL;
#pragma unroll
        for (int i = 0; i < 16; i++) {
            ulonglong2 evA = rowA[i];
            ulonglong2 evB = rowB[i];
            unsigned long long z0a = zp0[2 * i], z0b = zp0[2 * i + 1];
            unsigned long long z1a = zp1[2 * i], z1b = zp1[2 * i + 1];
            a00 = fma2(z0a, evA.x, a00);
            a01 = fma2(z0b, evA.y, a01);
            a10 = fma2(z1a, evA.x, a10);
            a11 = fma2(z1b, evA.y, a11);
            b00 = fma2(z0a, evB.x, b00);
            b01 = fma2(z0b, evB.y, b01);
            b10 = fma2(z1a, evB.x, b10);
            b11 = fma2(z1b, evB.y, b11);
        }
        // code k
        {
            float p0, p1, p2, p3;
            unpack2(a00, p0, p1);
            unpack2(a01, p2, p3);
            float dot  = __fadd_rn(__fadd_rn(p0, p1), __fadd_rn(p2, p3));
            float dist = __fsub_rn(__fadd_rn(sumz0, seA), __fmul_rn(2.0f, dot));
            if (dist < best0) { best0 = dist; bidx0 = k; }
        }
        {
            float p0, p1, p2, p3;
            unpack2(a10, p0, p1);
            unpack2(a11, p2, p3);
            float dot  = __fadd_rn(__fadd_rn(p0, p1), __fadd_rn(p2, p3));
            float dist = __fsub_rn(__fadd_rn(sumz1, seA), __fmul_rn(2.0f, dot));
            if (dist < best1) { best1 = dist; bidx1 = k; }
        }
        // code k+1
        {
            float p0, p1, p2, p3;
            unpack2(b00, p0, p1);
            unpack2(b01, p2, p3);
            float dot  = __fadd_rn(__fadd_rn(p0, p1), __fadd_rn(p2, p3));
            float dist = __fsub_rn(__fadd_rn(sumz0, seB), __fmul_rn(2.0f, dot));
            if (dist < best0) { best0 = dist; bidx0 = k + 1; }
        }
        {
            float p0, p1, p2, p3;
            unpack2(b10, p0, p1);
            unpack2(b11, p2, p3);
            float dot  = __fadd_rn(__fadd_rn(p0, p1), __fadd_rn(p2, p3));
            float dist = __fsub_rn(__fadd_rn(sumz1, seB), __fmul_rn(2.0f, dot));
            if (dist < best1) { best1 = dist; bidx1 = k + 1; }
        }
    }

    s_idx[tid]       = bidx0;
    s_idx[tid + TPB] = bidx1;

    // ---- quantized_st = fl(z + fl(q - z)), accumulate (q - z)^2 ----
    float lsum0 = 0.f, lsum1 = 0.f;
    {
        float* qout = out + OFF_Q + zb0;
        const float* erow = s_emb + bidx0 * D_DIM;
#pragma unroll
        for (int i = 0; i < 32; i++) {
            float zlo, zhi;
            unpack2(zp0[i], zlo, zhi);
            float d0 = __fsub_rn(erow[2 * i],     zlo);
            float d1 = __fsub_rn(erow[2 * i + 1], zhi);
            lsum0 += d0 * d0 + d1 * d1;
            qout[(2 * i) * 4096]     = __fadd_rn(zlo, d0);
            qout[(2 * i + 1) * 4096] = __fadd_rn(zhi, d1);
        }
    }
    {
        float* qout = out + OFF_Q + zb1;
        const float* erow = s_emb + bidx1 * D_DIM;
#pragma unroll
        for (int i = 0; i < 32; i++) {
            float zlo, zhi;
            unpack2(zp1[i], zlo, zhi);
            float d0 = __fsub_rn(erow[2 * i],     zlo);
            float d1 = __fsub_rn(erow[2 * i + 1], zhi);
            lsum1 += d0 * d0 + d1 * d1;
            qout[(2 * i) * 4096]     = __fadd_rn(zlo, d0);
            qout[(2 * i + 1) * 4096] = __fadd_rn(zhi, d1);
        }
    }

    out[OFF_IDX + (size_t)n0] = (float)bidx0;
    out[OFF_IDX + (size_t)n1] = (float)bidx1;
    atomicAdd(&g_s.counts[bidx0], 1);
    atomicAdd(&g_s.counts[bidx1], 1);

    // ---- block-reduce squared error (double), one atomic per block ----
    s_red[tid] = (double)lsum0 + (double)lsum1;
    __syncthreads();                 // also publishes s_idx
#pragma unroll
    for (int off = 128; off > 0; off >>= 1) {
        if (tid < off) s_red[tid] += s_red[tid + off];
        __syncthreads();
    }
    if (tid == 0) atomicAdd(&g_s.sumsq, s_red[0]);

    // ---- cooperative coalesced one-hot writes (float2: OFF_ENC is 8B-aligned) ----
    const int lane = tid & 31;
    const int warp = tid >> 5;
    const size_t enc_base = OFF_ENC + (size_t)(blockIdx.x * PIX_PER_BLK) * K_CODES;
    for (int r = warp * 64; r < warp * 64 + 64; r++) {
        const int target = s_idx[r];
        float2* rowp = (float2*)(out + enc_base + (size_t)r * K_CODES);
#pragma unroll
        for (int j = lane; j < 256; j += 32) {
            int c0 = j * 2;
            float2 v;
            v.x = (c0     == target) ? 1.f : 0.f;
            v.y = (c0 + 1 == target) ? 1.f : 0.f;
            rowp[j] = v;
        }
    }

    // ---- last block finalizes loss + perplexity ----
    __shared__ int s_last;
    __threadfence();
    __syncthreads();
    if (tid == 0) s_last = (atomicAdd(&g_s.ticket, 1) == NBLK - 1) ? 1 : 0;
    __syncthreads();
    if (s_last) {
        __threadfence();
        double t = 0.0;
        for (int r = tid; r < K_CODES; r += TPB) {
            float pf = (float)g_s.counts[r] * (1.0f / 131072.0f);
            t += (double)(pf * logf(pf + 1e-10f));
        }
        s_red[tid] = t;
        __syncthreads();
#pragma unroll
        for (int off = 128; off > 0; off >>= 1) {
            if (tid < off) s_red[tid] += s_red[tid + off];
            __syncthreads();
        }
        if (tid == 0) {
            out[OFF_PERP] = expf((float)(-s_red[0]));
            double m = g_s.sumsq / 8388608.0;
            float mf = (float)m;
            out[OFF_LOSS] = __fadd_rn(mf, __fmul_rn(0.25f, mf));
        }
    }
}

extern "C" void kernel_launch(void* const* d_in, const int* in_sizes, int n_in,
                              void* d_out, int out_size) {
    const float* z   = (const float*)d_in[0];   // latent_z [32,64,64,64]
    const float* emb = (const float*)d_in[1];   // embedding [512,64]
    float* out = (float*)d_out;

    void* sp = nullptr;
    cudaGetSymbolAddress(&sp, g_s);
    cudaMemsetAsync(sp, 0, sizeof(Scratch), 0);

    const int dyn_smem = 135168;  // 128KB codebook + 2KB norms + 2KB idx
    cudaFuncSetAttribute(vq_fused, cudaFuncAttributeMaxDynamicSharedMemorySize, dyn_smem);
    vq_fused<<<NBLK, TPB, dyn_smem>>>(z, emb, out);
}

// round 14
// speedup vs baseline: 1.4223x; 1.0920x over previous
#include <cuda_runtime.h>
#include <cstdint>

// Problem constants
#define N_PIXT  131072      // 32 * 64 * 64 pixels (B*H*W)
#define KC      512
#define DD      64
#define TPB     256
#define PIX_PER_BLK 512
#define NBLK    (N_PIXT / PIX_PER_BLK)   // 256
#define MARGIN  4e-3f
#define CAND_CAP 32

// Output layout (float32 concat in reference return order):
#define OFF_LOSS 0ULL
#define OFF_Q    1ULL
#define OFF_PERP 8388609ULL
#define OFF_ENC  8388610ULL
#define OFF_IDX  75497474ULL

struct Scratch { int counts[KC]; double sumsq; int ticket; };
__device__ Scratch g_s;

// smem byte offsets
enum : uint32_t {
    SM_E8   = 0,        // int8 codebook: 512 x 16 u32 = 32768
    SM_SE   = 32768,    // 512 f32 = 2048
    SM_CAND = 34816,    // 512 pix x 32 u16 = 32768
    SM_IDX  = 67584,    // 512 i32 = 2048
    SM_TOT  = 69632
};

// ---------- packed f32x2 helpers ----------
__device__ __forceinline__ unsigned long long fma2(unsigned long long a,
                                                   unsigned long long b,
                                                   unsigned long long c) {
    unsigned long long d;
    asm("fma.rn.f32x2 %0, %1, %2, %3;" : "=l"(d) : "l"(a), "l"(b), "l"(c));
    return d;
}
__device__ __forceinline__ unsigned long long pack2(float lo, float hi) {
    unsigned long long d;
    asm("mov.b64 %0, {%1, %2};" : "=l"(d) : "f"(lo), "f"(hi));
    return d;
}
__device__ __forceinline__ void unpack2(unsigned long long v, float& lo, float& hi) {
    asm("mov.b64 {%0, %1}, %2;" : "=f"(lo), "=f"(hi) : "l"(v));
}
__device__ __forceinline__ uint32_t packb(int a, int b, int c, int d) {
    return (uint32_t)(a & 0xFF) | ((uint32_t)(b & 0xFF) << 8) |
           ((uint32_t)(c & 0xFF) << 16) | ((uint32_t)(d & 0xFF) << 24);
}

// Exact distance, bit-identical to the R8-passing kernel's chain.
// e row read from global fp32 (same bits as the old smem copy).
__device__ __forceinline__ float exact_dist(const unsigned long long* zp, float sumz,
                                            float se, const float* erow) {
    unsigned long long a0 = 0ULL, a1 = 0ULL;
    const float4* e4 = (const float4*)erow;
#pragma unroll
    for (int i = 0; i < 16; i++) {
        float4 v = e4[i];
        a0 = fma2(zp[2 * i],     pack2(v.x, v.y), a0);
        a1 = fma2(zp[2 * i + 1], pack2(v.z, v.w), a1);
    }
    float p0, p1, p2, p3;
    unpack2(a0, p0, p1);
    unpack2(a1, p2, p3);
    float dot = __fadd_rn(__fadd_rn(p0, p1), __fadd_rn(p2, p3));
    return __fsub_rn(__fadd_rn(sumz, se), __fmul_rn(2.0f, dot));
}

extern __shared__ float4 smem4[];

__global__ __launch_bounds__(TPB, 2) void vq_dp4(const float* __restrict__ z,
                                                 const float* __restrict__ emb,
                                                 float* __restrict__ out) {
    char* smem = (char*)smem4;
    uint32_t*       s_e8 = (uint32_t*)(smem + SM_E8);
    float*          s_se = (float*)   (smem + SM_SE);
    unsigned short* s_cd = (unsigned short*)(smem + SM_CAND);
    int*            s_if = (int*)     (smem + SM_IDX);
    __shared__ double s_red[TPB];

    const int tid = threadIdx.x;
    const int wid = tid >> 5, lane = tid & 31;

    // ---- stage + quantize codebook, exact se (sequential ref order) ----
    for (int r = tid; r < KC; r += TPB) {
        const float4* er = (const float4*)(emb + r * DD);
        uint32_t* dst = s_e8 + r * 16;
        float se = 0.f;
#pragma unroll
        for (int i = 0; i < 16; i++) {
            float4 v = er[i];
            se = __fadd_rn(se, __fmul_rn(v.x, v.x));
            se = __fadd_rn(se, __fmul_rn(v.y, v.y));
            se = __fadd_rn(se, __fmul_rn(v.z, v.z));
            se = __fadd_rn(se, __fmul_rn(v.w, v.w));
            dst[i] = packb(__float2int_rn(v.x * 65024.0f), __float2int_rn(v.y * 65024.0f),
                           __float2int_rn(v.z * 65024.0f), __float2int_rn(v.w * 65024.0f));
        }
        s_se[r] = se;
    }
    __syncthreads();

    // ---- load + quantize z for 2 pixels; exact sumz (ref order) ----
    const int n0 = blockIdx.x * PIX_PER_BLK + tid;
    const int n1 = n0 + TPB;
    const size_t zb0 = (size_t)(n0 >> 12) * 262144 + (size_t)(n0 & 4095);
    const size_t zb1 = (size_t)(n1 >> 12) * 262144 + (size_t)(n1 & 4095);
    const float* zg0 = z + zb0;
    const float* zg1 = z + zb1;

    uint32_t q0[16], q1[16];
    float sumz0, sumz1, cp0, cp1;
    {
        float t[64];
        float sz = 0.f, mx = 0.f;
#pragma unroll
        for (int i = 0; i < 32; i++) {
            float a = zg0[(2 * i) * 4096];
            float c = zg0[(2 * i + 1) * 4096];
            sz = __fadd_rn(sz, __fmul_rn(a, a));
            sz = __fadd_rn(sz, __fmul_rn(c, c));
            mx = fmaxf(mx, fmaxf(fabsf(a), fabsf(c)));
            t[2 * i] = a; t[2 * i + 1] = c;
        }
        sumz0 = sz;
        float zs = (mx > 0.f) ? 127.0f / mx : 0.f;
        cp0 = (mx > 0.f) ? -2.0f * (mx / 127.0f) * (1.0f / 65024.0f) : 0.f;
#pragma unroll
        for (int w = 0; w < 16; w++)
            q0[w] = packb(__float2int_rn(t[4 * w] * zs),     __float2int_rn(t[4 * w + 1] * zs),
                          __float2int_rn(t[4 * w + 2] * zs), __float2int_rn(t[4 * w + 3] * zs));
    }
    {
        float t[64];
        float sz = 0.f, mx = 0.f;
#pragma unroll
        for (int i = 0; i < 32; i++) {
            float a = zg1[(2 * i) * 4096];
            float c = zg1[(2 * i + 1) * 4096];
            sz = __fadd_rn(sz, __fmul_rn(a, a));
            sz = __fadd_rn(sz, __fmul_rn(c, c));
            mx = fmaxf(mx, fmaxf(fabsf(a), fabsf(c)));
            t[2 * i] = a; t[2 * i + 1] = c;
        }
        sumz1 = sz;
        float zs = (mx > 0.f) ? 127.0f / mx : 0.f;
        cp1 = (mx > 0.f) ? -2.0f * (mx / 127.0f) * (1.0f / 65024.0f) : 0.f;
#pragma unroll
        for (int w = 0; w < 16; w++)
            q1[w] = packb(__float2int_rn(t[4 * w] * zs),     __float2int_rn(t[4 * w + 1] * zs),
                          __float2int_rn(t[4 * w + 2] * zs), __float2int_rn(t[4 * w + 3] * zs));
    }

    // ---- dp4a screen over 512 codes, running-best + margin collection ----
    float best0 = 3.4e38f, best1 = 3.4e38f;
    float lim0 = 3.4e38f, lim1 = 3.4e38f;
    int bk0 = 0, bk1 = 0, c0 = 0, c1 = 0;
    unsigned short* cd0 = s_cd + tid * CAND_CAP;
    unsigned short* cd1 = s_cd + (tid + TPB) * CAND_CAP;
    const uint4* e8 = (const uint4*)s_e8;
#pragma unroll 2
    for (int k = 0; k < KC; k++) {
        const uint4* r = e8 + k * 4;
        uint4 w0 = r[0], w1 = r[1], w2 = r[2], w3 = r[3];
        int d0 = 0, d1 = 0;
        d0 = __dp4a((int)w0.x, (int)q0[0],  d0); d1 = __dp4a((int)w0.x, (int)q1[0],  d1);
        d0 = __dp4a((int)w0.y, (int)q0[1],  d0); d1 = __dp4a((int)w0.y, (int)q1[1],  d1);
        d0 = __dp4a((int)w0.z, (int)q0[2],  d0); d1 = __dp4a((int)w0.z, (int)q1[2],  d1);
        d0 = __dp4a((int)w0.w, (int)q0[3],  d0); d1 = __dp4a((int)w0.w, (int)q1[3],  d1);
        d0 = __dp4a((int)w1.x, (int)q0[4],  d0); d1 = __dp4a((int)w1.x, (int)q1[4],  d1);
        d0 = __dp4a((int)w1.y, (int)q0[5],  d0); d1 = __dp4a((int)w1.y, (int)q1[5],  d1);
        d0 = __dp4a((int)w1.z, (int)q0[6],  d0); d1 = __dp4a((int)w1.z, (int)q1[6],  d1);
        d0 = __dp4a((int)w1.w, (int)q0[7],  d0); d1 = __dp4a((int)w1.w, (int)q1[7],  d1);
        d0 = __dp4a((int)w2.x, (int)q0[8],  d0); d1 = __dp4a((int)w2.x, (int)q1[8],  d1);
        d0 = __dp4a((int)w2.y, (int)q0[9],  d0); d1 = __dp4a((int)w2.y, (int)q1[9],  d1);
        d0 = __dp4a((int)w2.z, (int)q0[10], d0); d1 = __dp4a((int)w2.z, (int)q1[10], d1);
        d0 = __dp4a((int)w2.w, (int)q0[11], d0); d1 = __dp4a((int)w2.w, (int)q1[11], d1);
        d0 = __dp4a((int)w3.x, (int)q0[12], d0); d1 = __dp4a((int)w3.x, (int)q1[12], d1);
        d0 = __dp4a((int)w3.y, (int)q0[13], d0); d1 = __dp4a((int)w3.y, (int)q1[13], d1);
        d0 = __dp4a((int)w3.z, (int)q0[14], d0); d1 = __dp4a((int)w3.z, (int)q1[14], d1);
        d0 = __dp4a((int)w3.w, (int)q0[15], d0); d1 = __dp4a((int)w3.w, (int)q1[15], d1);
        const float se = s_se[k];
        float s0 = __fmaf_rn((float)d0, cp0, se);
        float s1 = __fmaf_rn((float)d1, cp1, se);
        if (s0 < lim0) {
            if (c0 < CAND_CAP) cd0[c0] = (unsigned short)k;
            c0++;
            if (s0 < best0) { best0 = s0; bk0 = k; lim0 = best0 + MARGIN; }
        }
        if (s1 < lim1) {
            if (c1 < CAND_CAP) cd1[c1] = (unsigned short)k;
            c1++;
            if (s1 < best1) { best1 = s1; bk1 = k; lim1 = best1 + MARGIN; }
        }
    }
    if (c0 > CAND_CAP) c0 = CAND_CAP;
    if (c1 > CAND_CAP) c1 = CAND_CAP;

    // ---- per-pixel rescreen + outputs (sequential to cap registers) ----
    float lsum = 0.f;
#pragma unroll 1
    for (int pp = 0; pp < 2; pp++) {
        const float* zg  = pp ? zg1 : zg0;
        const size_t zb  = pp ? zb1 : zb0;
        const int    n   = pp ? n1 : n0;
        const float  sumz = pp ? sumz1 : sumz0;
        const float  bestv = pp ? best1 : best0;
        const float  cp = pp ? cp1 : cp0;
        const uint32_t* q = pp ? q1 : q0;
        const unsigned short* cd = pp ? cd1 : cd0;
        const int    cnt = pp ? c1 : c0;
        int bk = pp ? bk1 : bk0;

        // reload z as packed pairs (identical bits -> identical chain)
        unsigned long long zp[32];
#pragma unroll
        for (int i = 0; i < 32; i++)
            zp[i] = pack2(zg[(2 * i) * 4096], zg[(2 * i + 1) * 4096]);

        if (cnt > 1) {
            const float lim = bestv + MARGIN;
            float bex = 3.4e38f;
            int bkx = bk;
            for (int i = 0; i < cnt; i++) {
                const int k = cd[i];
                // cheap filter: recompute approx score vs final best
                const uint4* r = e8 + k * 4;
                uint4 w0 = r[0], w1 = r[1], w2 = r[2], w3 = r[3];
                int d = 0;
                d = __dp4a((int)w0.x, (int)q[0],  d); d = __dp4a((int)w0.y, (int)q[1],  d);
                d = __dp4a((int)w0.z, (int)q[2],  d); d = __dp4a((int)w0.w, (int)q[3],  d);
                d = __dp4a((int)w1.x, (int)q[4],  d); d = __dp4a((int)w1.y, (int)q[5],  d);
                d = __dp4a((int)w1.z, (int)q[6],  d); d = __dp4a((int)w1.w, (int)q[7],  d);
                d = __dp4a((int)w2.x, (int)q[8],  d); d = __dp4a((int)w2.y, (int)q[9],  d);
                d = __dp4a((int)w2.z, (int)q[10], d); d = __dp4a((int)w2.w, (int)q[11], d);
                d = __dp4a((int)w3.x, (int)q[12], d); d = __dp4a((int)w3.y, (int)q[13], d);
                d = __dp4a((int)w3.z, (int)q[14], d); d = __dp4a((int)w3.w, (int)q[15], d);
                float s = __fmaf_rn((float)d, cp, s_se[k]);
                if (s >= lim) continue;
                float dist = exact_dist(zp, sumz, s_se[k], emb + k * DD);
                if (dist < bex) { bex = dist; bkx = k; }
            }
            bk = bkx;
        }

        s_if[pp * TPB + tid] = bk;
        out[OFF_IDX + (size_t)n] = (float)bk;
        atomicAdd(&g_s.counts[bk], 1);

        // quantized_st = fl(z + fl(q - z)), accumulate (q - z)^2  (R8 chain)
        float* qout = out + OFF_Q + zb;
        const float2* er2 = (const float2*)(emb + bk * DD);
#pragma unroll
        for (int i = 0; i < 32; i++) {
            float zlo, zhi;
            unpack2(zp[i], zlo, zhi);
            float2 e = er2[i];
            float d0 = __fsub_rn(e.x, zlo);
            float d1 = __fsub_rn(e.y, zhi);
            lsum += d0 * d0 + d1 * d1;
            qout[(2 * i) * 4096]     = __fadd_rn(zlo, d0);
            qout[(2 * i + 1) * 4096] = __fadd_rn(zhi, d1);
        }
    }

    // ---- block-reduce squared error (double), one atomic per block ----
    s_red[tid] = (double)lsum;
    __syncthreads();                 // also publishes s_if
#pragma unroll
    for (int off = 128; off > 0; off >>= 1) {
        if (tid < off) s_red[tid] += s_red[tid + off];
        __syncthreads();
    }
    if (tid == 0) atomicAdd(&g_s.sumsq, s_red[0]);

    // ---- cooperative one-hot writes (float2: OFF_ENC is 8B-aligned) ----
    const size_t enc_base = OFF_ENC + (size_t)(blockIdx.x * PIX_PER_BLK) * KC;
    for (int r = wid * 64; r < wid * 64 + 64; r++) {
        const int target = s_if[r];
        float2* rowp = (float2*)(out + enc_base + (size_t)r * KC);
#pragma unroll
        for (int j = lane; j < 256; j += 32) {
            int cc = j * 2;
            float2 v;
            v.x = (cc     == target) ? 1.f : 0.f;
            v.y = (cc + 1 == target) ? 1.f : 0.f;
            rowp[j] = v;
        }
    }

    // ---- last block finalizes loss + perplexity ----
    __shared__ int s_last;
    __threadfence();
    __syncthreads();
    if (tid == 0) s_last = (atomicAdd(&g_s.ticket, 1) == NBLK - 1) ? 1 : 0;
    __syncthreads();
    if (s_last) {
        __threadfence();
        double t = 0.0;
        for (int r = tid; r < KC; r += TPB) {
            float pf = (float)g_s.counts[r] * (1.0f / 131072.0f);
            t += (double)(pf * logf(pf + 1e-10f));
        }
        s_red[tid] = t;
        __syncthreads();
#pragma unroll
        for (int off = 128; off > 0; off >>= 1) {
            if (tid < off) s_red[tid] += s_red[tid + off];
            __syncthreads();
        }
        if (tid == 0) {
            out[OFF_PERP] = expf((float)(-s_red[0]));
            double m = g_s.sumsq / 8388608.0;
            float mf = (float)m;
            out[OFF_LOSS] = __fadd_rn(mf, __fmul_rn(0.25f, mf));
        }
    }
}

extern "C" void kernel_launch(void* const* d_in, const int* in_sizes, int n_in,
                              void* d_out, int out_size) {
    const float* z   = (const float*)d_in[0];   // latent_z [32,64,64,64]
    const float* emb = (const float*)d_in[1];   // embedding [512,64]
    float* out = (float*)d_out;

    void* sp = nullptr;
    cudaGetSymbolAddress(&sp, g_s);
    cudaMemsetAsync(sp, 0, sizeof(Scratch), 0);

    cudaFuncSetAttribute(vq_dp4, cudaFuncAttributeMaxDynamicSharedMemorySize, SM_TOT);
    vq_dp4<<<NBLK, TPB, SM_TOT>>>(z, emb, out);
}

// round 15
// speedup vs baseline: 1.4817x; 1.0418x over previous
#include <cuda_runtime.h>
#include <cstdint>

// Problem constants
#define N_PIXT  131072      // 32 * 64 * 64 pixels (B*H*W)
#define KC      512
#define DD      64
#define TPB     256
#define PIX_PER_BLK 512
#define NBLK    (N_PIXT / PIX_PER_BLK)   // 256
#define MARGIN  4e-3f
#define CAND_CAP 32

// Output layout (float32 concat in reference return order):
#define OFF_LOSS 0ULL
#define OFF_Q    1ULL
#define OFF_PERP 8388609ULL
#define OFF_ENC  8388610ULL
#define OFF_IDX  75497474ULL

struct Scratch { int counts[KC]; double sumsq; int ticket; };
__device__ Scratch g_s;

// smem byte offsets
enum : uint32_t {
    SM_E8   = 0,        // int8 codebook: 512 x 16 u32 = 32768
    SM_SE   = 32768,    // 512 f32 = 2048
    SM_CAND = 34816,    // 512 pix x 32 u16 = 32768
    SM_IDX  = 67584,    // 512 i32 = 2048
    SM_TOT  = 69632
};

// ---------- packed f32x2 helpers ----------
__device__ __forceinline__ unsigned long long fma2(unsigned long long a,
                                                   unsigned long long b,
                                                   unsigned long long c) {
    unsigned long long d;
    asm("fma.rn.f32x2 %0, %1, %2, %3;" : "=l"(d) : "l"(a), "l"(b), "l"(c));
    return d;
}
__device__ __forceinline__ unsigned long long pack2(float lo, float hi) {
    unsigned long long d;
    asm("mov.b64 %0, {%1, %2};" : "=l"(d) : "f"(lo), "f"(hi));
    return d;
}
__device__ __forceinline__ void unpack2(unsigned long long v, float& lo, float& hi) {
    asm("mov.b64 {%0, %1}, %2;" : "=f"(lo), "=f"(hi) : "l"(v));
}
__device__ __forceinline__ uint32_t packb(int a, int b, int c, int d) {
    return (uint32_t)(a & 0xFF) | ((uint32_t)(b & 0xFF) << 8) |
           ((uint32_t)(c & 0xFF) << 16) | ((uint32_t)(d & 0xFF) << 24);
}

// Exact distance, bit-identical to the R8-passing kernel's chain.
__device__ __forceinline__ float exact_dist(const unsigned long long* zp, float sumz,
                                            float se, const float* erow) {
    unsigned long long a0 = 0ULL, a1 = 0ULL;
    const float4* e4 = (const float4*)erow;
#pragma unroll
    for (int i = 0; i < 16; i++) {
        float4 v = e4[i];
        a0 = fma2(zp[2 * i],     pack2(v.x, v.y), a0);
        a1 = fma2(zp[2 * i + 1], pack2(v.z, v.w), a1);
    }
    float p0, p1, p2, p3;
    unpack2(a0, p0, p1);
    unpack2(a1, p2, p3);
    float dot = __fadd_rn(__fadd_rn(p0, p1), __fadd_rn(p2, p3));
    return __fsub_rn(__fadd_rn(sumz, se), __fmul_rn(2.0f, dot));
}

extern __shared__ float4 smem4[];

__global__ __launch_bounds__(TPB, 2) void vq_dp4(const float* __restrict__ z,
                                                 const float* __restrict__ emb,
                                                 float* __restrict__ out) {
    char* smem = (char*)smem4;
    uint32_t*       s_e8 = (uint32_t*)(smem + SM_E8);
    float*          s_se = (float*)   (smem + SM_SE);
    unsigned short* s_cd = (unsigned short*)(smem + SM_CAND);
    int*            s_if = (int*)     (smem + SM_IDX);
    __shared__ double s_red[TPB];

    const int tid = threadIdx.x;
    const int wid = tid >> 5, lane = tid & 31;

    // ---- stage + quantize codebook, exact se (sequential ref order) ----
    for (int r = tid; r < KC; r += TPB) {
        const float4* er = (const float4*)(emb + r * DD);
        uint32_t* dst = s_e8 + r * 16;
        float se = 0.f;
#pragma unroll
        for (int i = 0; i < 16; i++) {
            float4 v = er[i];
            se = __fadd_rn(se, __fmul_rn(v.x, v.x));
            se = __fadd_rn(se, __fmul_rn(v.y, v.y));
            se = __fadd_rn(se, __fmul_rn(v.z, v.z));
            se = __fadd_rn(se, __fmul_rn(v.w, v.w));
            dst[i] = packb(__float2int_rn(v.x * 65024.0f), __float2int_rn(v.y * 65024.0f),
                           __float2int_rn(v.z * 65024.0f), __float2int_rn(v.w * 65024.0f));
        }
        s_se[r] = se;
    }
    __syncthreads();

    // ---- load + quantize z for 2 pixels; exact sumz (ref order) ----
    const int n0 = blockIdx.x * PIX_PER_BLK + tid;
    const int n1 = n0 + TPB;
    const size_t zb0 = (size_t)(n0 >> 12) * 262144 + (size_t)(n0 & 4095);
    const size_t zb1 = (size_t)(n1 >> 12) * 262144 + (size_t)(n1 & 4095);
    const float* zg0 = z + zb0;
    const float* zg1 = z + zb1;

    uint32_t q0[16], q1[16];
    float sumz0, sumz1, cp0, cp1;
    {
        float t[64];
        float sz = 0.f, mx = 0.f;
#pragma unroll
        for (int i = 0; i < 32; i++) {
            float a = zg0[(2 * i) * 4096];
            float c = zg0[(2 * i + 1) * 4096];
            sz = __fadd_rn(sz, __fmul_rn(a, a));
            sz = __fadd_rn(sz, __fmul_rn(c, c));
            mx = fmaxf(mx, fmaxf(fabsf(a), fabsf(c)));
            t[2 * i] = a; t[2 * i + 1] = c;
        }
        sumz0 = sz;
        float zs = (mx > 0.f) ? 127.0f / mx : 0.f;
        cp0 = (mx > 0.f) ? -2.0f * (mx / 127.0f) * (1.0f / 65024.0f) : 0.f;
#pragma unroll
        for (int w = 0; w < 16; w++)
            q0[w] = packb(__float2int_rn(t[4 * w] * zs),     __float2int_rn(t[4 * w + 1] * zs),
                          __float2int_rn(t[4 * w + 2] * zs), __float2int_rn(t[4 * w + 3] * zs));
    }
    {
        float t[64];
        float sz = 0.f, mx = 0.f;
#pragma unroll
        for (int i = 0; i < 32; i++) {
            float a = zg1[(2 * i) * 4096];
            float c = zg1[(2 * i + 1) * 4096];
            sz = __fadd_rn(sz, __fmul_rn(a, a));
            sz = __fadd_rn(sz, __fmul_rn(c, c));
            mx = fmaxf(mx, fmaxf(fabsf(a), fabsf(c)));
            t[2 * i] = a; t[2 * i + 1] = c;
        }
        sumz1 = sz;
        float zs = (mx > 0.f) ? 127.0f / mx : 0.f;
        cp1 = (mx > 0.f) ? -2.0f * (mx / 127.0f) * (1.0f / 65024.0f) : 0.f;
#pragma unroll
        for (int w = 0; w < 16; w++)
            q1[w] = packb(__float2int_rn(t[4 * w] * zs),     __float2int_rn(t[4 * w + 1] * zs),
                          __float2int_rn(t[4 * w + 2] * zs), __float2int_rn(t[4 * w + 3] * zs));
    }

    // ---- dp4a screen: 4 independent accum chains/pixel, prefetched rows,
    //      branchless candidate collection ----
    float best0 = 3.4e38f, best1 = 3.4e38f;
    float lim0 = 3.4e38f, lim1 = 3.4e38f;
    int bk0 = 0, bk1 = 0, c0 = 0, c1 = 0;
    unsigned short* cd0 = s_cd + tid * CAND_CAP;
    unsigned short* cd1 = s_cd + (tid + TPB) * CAND_CAP;
    const uint4* e8 = (const uint4*)s_e8;

    uint4 w0 = e8[0], w1 = e8[1], w2 = e8[2], w3 = e8[3];
#pragma unroll 2
    for (int k = 0; k < KC; k++) {
        // prefetch next row (wraps harmlessly at k=511)
        const uint4* nr = e8 + ((k + 1) & (KC - 1)) * 4;
        uint4 x0 = nr[0], x1 = nr[1], x2 = nr[2], x3 = nr[3];
        const float se = s_se[k];

        int a0 = 0, a1 = 0, a2 = 0, a3 = 0;      // pixel0: 4 chains of depth 4
        int b0 = 0, b1 = 0, b2 = 0, b3 = 0;      // pixel1
        a0 = __dp4a((int)w0.x, (int)q0[0],  a0); b0 = __dp4a((int)w0.x, (int)q1[0],  b0);
        a1 = __dp4a((int)w0.y, (int)q0[1],  a1); b1 = __dp4a((int)w0.y, (int)q1[1],  b1);
        a2 = __dp4a((int)w0.z, (int)q0[2],  a2); b2 = __dp4a((int)w0.z, (int)q1[2],  b2);
        a3 = __dp4a((int)w0.w, (int)q0[3],  a3); b3 = __dp4a((int)w0.w, (int)q1[3],  b3);
        a0 = __dp4a((int)w1.x, (int)q0[4],  a0); b0 = __dp4a((int)w1.x, (int)q1[4],  b0);
        a1 = __dp4a((int)w1.y, (int)q0[5],  a1); b1 = __dp4a((int)w1.y, (int)q1[5],  b1);
        a2 = __dp4a((int)w1.z, (int)q0[6],  a2); b2 = __dp4a((int)w1.z, (int)q1[6],  b2);
        a3 = __dp4a((int)w1.w, (int)q0[7],  a3); b3 = __dp4a((int)w1.w, (int)q1[7],  b3);
        a0 = __dp4a((int)w2.x, (int)q0[8],  a0); b0 = __dp4a((int)w2.x, (int)q1[8],  b0);
        a1 = __dp4a((int)w2.y, (int)q0[9],  a1); b1 = __dp4a((int)w2.y, (int)q1[9],  b1);
        a2 = __dp4a((int)w2.z, (int)q0[10], a2); b2 = __dp4a((int)w2.z, (int)q1[10], b2);
        a3 = __dp4a((int)w2.w, (int)q0[11], a3); b3 = __dp4a((int)w2.w, (int)q1[11], b3);
        a0 = __dp4a((int)w3.x, (int)q0[12], a0); b0 = __dp4a((int)w3.x, (int)q1[12], b0);
        a1 = __dp4a((int)w3.y, (int)q0[13], a1); b1 = __dp4a((int)w3.y, (int)q1[13], b1);
        a2 = __dp4a((int)w3.z, (int)q0[14], a2); b2 = __dp4a((int)w3.z, (int)q1[14], b2);
        a3 = __dp4a((int)w3.w, (int)q0[15], a3); b3 = __dp4a((int)w3.w, (int)q1[15], b3);

        int d0 = (a0 + a1) + (a2 + a3);
        int d1 = (b0 + b1) + (b2 + b3);
        float s0 = __fmaf_rn((float)d0, cp0, se);
        float s1 = __fmaf_rn((float)d1, cp1, se);

        // branchless collect + best update (ascending-k, strict <)
        bool t0 = s0 < lim0;
        bool t1 = s1 < lim1;
        if (t0) cd0[c0 & (CAND_CAP - 1)] = (unsigned short)k;
        if (t1) cd1[c1 & (CAND_CAP - 1)] = (unsigned short)k;
        c0 += t0; c1 += t1;
        bool nb0 = s0 < best0;
        bool nb1 = s1 < best1;
        best0 = nb0 ? s0 : best0;  bk0 = nb0 ? k : bk0;
        best1 = nb1 ? s1 : best1;  bk1 = nb1 ? k : bk1;
        lim0 = best0 + MARGIN;
        lim1 = best1 + MARGIN;

        w0 = x0; w1 = x1; w2 = x2; w3 = x3;
    }
    if (c0 > CAND_CAP) c0 = CAND_CAP;
    if (c1 > CAND_CAP) c1 = CAND_CAP;

    // ---- per-pixel rescreen + outputs (sequential to cap registers) ----
    float lsum = 0.f;
#pragma unroll 1
    for (int pp = 0; pp < 2; pp++) {
        const float* zg  = pp ? zg1 : zg0;
        const size_t zb  = pp ? zb1 : zb0;
        const int    n   = pp ? n1 : n0;
        const float  sumz = pp ? sumz1 : sumz0;
        const float  bestv = pp ? best1 : best0;
        const float  cp = pp ? cp1 : cp0;
        const uint32_t* q = pp ? q1 : q0;
        const unsigned short* cd = pp ? cd1 : cd0;
        const int    cnt = pp ? c1 : c0;
        int bk = pp ? bk1 : bk0;

        // reload z as packed pairs (identical bits -> identical chain)
        unsigned long long zp[32];
#pragma unroll
        for (int i = 0; i < 32; i++)
            zp[i] = pack2(zg[(2 * i) * 4096], zg[(2 * i + 1) * 4096]);

        if (cnt > 1) {
            const float lim = bestv + MARGIN;
            float bex = 3.4e38f;
            int bkx = bk;
            for (int i = 0; i < cnt; i++) {
                const int k = cd[i];
                // cheap filter: recompute approx score vs final best
                const uint4* r = (const uint4*)s_e8 + k * 4;
                uint4 v0 = r[0], v1 = r[1], v2 = r[2], v3 = r[3];
                int d = 0;
                d = __dp4a((int)v0.x, (int)q[0],  d); d = __dp4a((int)v0.y, (int)q[1],  d);
                d = __dp4a((int)v0.z, (int)q[2],  d); d = __dp4a((int)v0.w, (int)q[3],  d);
                d = __dp4a((int)v1.x, (int)q[4],  d); d = __dp4a((int)v1.y, (int)q[5],  d);
                d = __dp4a((int)v1.z, (int)q[6],  d); d = __dp4a((int)v1.w, (int)q[7],  d);
                d = __dp4a((int)v2.x, (int)q[8],  d); d = __dp4a((int)v2.y, (int)q[9],  d);
                d = __dp4a((int)v2.z, (int)q[10], d); d = __dp4a((int)v2.w, (int)q[11], d);
                d = __dp4a((int)v3.x, (int)q[12], d); d = __dp4a((int)v3.y, (int)q[13], d);
                d = __dp4a((int)v3.z, (int)q[14], d); d = __dp4a((int)v3.w, (int)q[15], d);
                float s = __fmaf_rn((float)d, cp, s_se[k]);
                if (s >= lim) continue;
                float dist = exact_dist(zp, sumz, s_se[k], emb + k * DD);
                if (dist < bex) { bex = dist; bkx = k; }
            }
            bk = bkx;
        }

        s_if[pp * TPB + tid] = bk;
        out[OFF_IDX + (size_t)n] = (float)bk;
        atomicAdd(&g_s.counts[bk], 1);

        // quantized_st = fl(z + fl(q - z)), accumulate (q - z)^2  (R8 chain)
        float* qout = out + OFF_Q + zb;
        const float2* er2 = (const float2*)(emb + bk * DD);
#pragma unroll
        for (int i = 0; i < 32; i++) {
            float zlo, zhi;
            unpack2(zp[i], zlo, zhi);
            float2 e = er2[i];
            float d0 = __fsub_rn(e.x, zlo);
            float d1 = __fsub_rn(e.y, zhi);
            lsum += d0 * d0 + d1 * d1;
            qout[(2 * i) * 4096]     = __fadd_rn(zlo, d0);
            qout[(2 * i + 1) * 4096] = __fadd_rn(zhi, d1);
        }
    }

    // ---- block-reduce squared error (double), one atomic per block ----
    s_red[tid] = (double)lsum;
    __syncthreads();                 // also publishes s_if
#pragma unroll
    for (int off = 128; off > 0; off >>= 1) {
        if (tid < off) s_red[tid] += s_red[tid + off];
        __syncthreads();
    }
    if (tid == 0) atomicAdd(&g_s.sumsq, s_red[0]);

    // ---- cooperative one-hot writes (float2: OFF_ENC is 8B-aligned) ----
    const size_t enc_base = OFF_ENC + (size_t)(blockIdx.x * PIX_PER_BLK) * KC;
    for (int r = wid * 64; r < wid * 64 + 64; r++) {
        const int target = s_if[r];
        float2* rowp = (float2*)(out + enc_base + (size_t)r * KC);
#pragma unroll
        for (int j = lane; j < 256; j += 32) {
            int cc = j * 2;
            float2 v;
            v.x = (cc     == target) ? 1.f : 0.f;
            v.y = (cc + 1 == target) ? 1.f : 0.f;
            rowp[j] = v;
        }
    }

    // ---- last block finalizes loss + perplexity ----
    __shared__ int s_last;
    __threadfence();
    __syncthreads();
    if (tid == 0) s_last = (atomicAdd(&g_s.ticket, 1) == NBLK - 1) ? 1 : 0;
    __syncthreads();
    if (s_last) {
        __threadfence();
        double t = 0.0;
        for (int r = tid; r < KC; r += TPB) {
            float pf = (float)g_s.counts[r] * (1.0f / 131072.0f);
            t += (double)(pf * logf(pf + 1e-10f));
        }
        s_red[tid] = t;
        __syncthreads();
#pragma unroll
        for (int off = 128; off > 0; off >>= 1) {
            if (tid < off) s_red[tid] += s_red[tid + off];
            __syncthreads();
        }
        if (tid == 0) {
            out[OFF_PERP] = expf((float)(-s_red[0]));
            double m = g_s.sumsq / 8388608.0;
            float mf = (float)m;
            out[OFF_LOSS] = __fadd_rn(mf, __fmul_rn(0.25f, mf));
        }
    }
}

extern "C" void kernel_launch(void* const* d_in, const int* in_sizes, int n_in,
                              void* d_out, int out_size) {
    const float* z   = (const float*)d_in[0];   // latent_z [32,64,64,64]
    const float* emb = (const float*)d_in[1];   // embedding [512,64]
    float* out = (float*)d_out;

    void* sp = nullptr;
    cudaGetSymbolAddress(&sp, g_s);
    cudaMemsetAsync(sp, 0, sizeof(Scratch), 0);

    cudaFuncSetAttribute(vq_dp4, cudaFuncAttributeMaxDynamicSharedMemorySize, SM_TOT);
    vq_dp4<<<NBLK, TPB, SM_TOT>>>(z, emb, out);
}